// round 4
// baseline (speedup 1.0000x reference)
#include <cuda_runtime.h>
#include <cstdint>

#define BATCH   8
#define S_LEN   2048
#define EMB     512
#define HEADS   64
#define DK      8
#define NTOK    (BATCH * S_LEN)   // 16384

// Scrambled attention output (b, h*32 + s/64, (s%64)*8 + d), 33.5 MB scratch.
__device__ float g_Y[(size_t)NTOK * EMB];

// ---------------------------------------------------------------------------
// Packed f32x2 helpers (sm_103a; ptxas won't auto-fuse — must be inline PTX)
// ---------------------------------------------------------------------------
typedef unsigned long long u64;

__device__ __forceinline__ u64 pk2(float lo, float hi) {
    u64 r; asm("mov.b64 %0, {%1, %2};" : "=l"(r) : "f"(lo), "f"(hi)); return r;
}
__device__ __forceinline__ void upk2(u64 v, float& lo, float& hi) {
    asm("mov.b64 {%0, %1}, %2;" : "=f"(lo), "=f"(hi) : "l"(v));
}
__device__ __forceinline__ u64 fma2(u64 a, u64 b, u64 c) {
    u64 d; asm("fma.rn.f32x2 %0, %1, %2, %3;" : "=l"(d) : "l"(a), "l"(b), "l"(c)); return d;
}
__device__ __forceinline__ u64 mul2(u64 a, u64 b) {
    u64 d; asm("mul.rn.f32x2 %0, %1, %2;" : "=l"(d) : "l"(a), "l"(b)); return d;
}
__device__ __forceinline__ float ex2a(float x) {
    float r; asm("ex2.approx.f32 %0, %1;" : "=f"(r) : "f"(x)); return r;
}

// ---------------------------------------------------------------------------
// Kernel A: quantum projection + head-axis attention, single-pass softmax.
// (unchanged from R2 — 63us, fma-pipe-bound; next candidate for tensorization)
// ---------------------------------------------------------------------------
__global__ __launch_bounds__(256) void attn_kernel(const float* __restrict__ x,
                                                   const float* __restrict__ theta) {
    __shared__ __align__(16) float sproj[4][HEADS][DK];   // 8 KB

    const int tok_l = threadIdx.x >> 6;     // 0..3
    const int h     = threadIdx.x & 63;     // head row
    const int t     = (blockIdx.x << 2) + tok_l;
    const int b     = t >> 11;
    const int s     = t & 2047;

    const float4* xt  = (const float4*)(x + (size_t)t * EMB);
    const float4* th4 = (const float4*)theta;
    const float4 xa = xt[h * 2 + 0];
    const float4 xb = xt[h * 2 + 1];
    const float4 ta = th4[0];
    const float4 tb = th4[1];

    float p0 = cosf(xa.x + ta.x), p1 = cosf(xa.y + ta.y);
    float p2 = cosf(xa.z + ta.z), p3 = cosf(xa.w + ta.w);
    float p4 = cosf(xb.x + tb.x), p5 = cosf(xb.y + tb.y);
    float p6 = cosf(xb.z + tb.z), p7 = cosf(xb.w + tb.w);

    float4* sp = (float4*)&sproj[tok_l][h][0];
    sp[0] = make_float4(p0, p1, p2, p3);
    sp[1] = make_float4(p4, p5, p6, p7);
    __syncthreads();

    const u64 P01 = pk2(p0, p1), P23 = pk2(p2, p3);
    const u64 P45 = pk2(p4, p5), P67 = pk2(p6, p7);

    // scale = 1/sqrt(8) * log2(e)  (softmax scale folded into exp2;
    // |score*scale| <= 4.1 so no max-subtraction needed)
    const float SCALE = 0.35355339059327373f * 1.4426950408889634f;

    const ulonglong2* pj = (const ulonglong2*)&sproj[tok_l][0][0];

    float sum = 0.f;
    u64 A01 = 0, A23 = 0, A45 = 0, A67 = 0;

#pragma unroll 16
    for (int g = 0; g < 64; ++g) {
        ulonglong2 qa = pj[g * 2 + 0];
        ulonglong2 qb = pj[g * 2 + 1];

        u64 d2 = mul2(P01, qa.x);
        d2 = fma2(P23, qa.y, d2);
        d2 = fma2(P45, qb.x, d2);
        d2 = fma2(P67, qb.y, d2);
        float dlo, dhi; upk2(d2, dlo, dhi);

        float w = ex2a((dlo + dhi) * SCALE);
        sum += w;

        u64 ww = pk2(w, w);
        A01 = fma2(ww, qa.x, A01);
        A23 = fma2(ww, qa.y, A23);
        A45 = fma2(ww, qb.x, A45);
        A67 = fma2(ww, qb.y, A67);
    }

    const float inv = 1.0f / sum;
    float a0, a1, a2, a3, a4, a5, a6, a7;
    upk2(A01, a0, a1); upk2(A23, a2, a3);
    upk2(A45, a4, a5); upk2(A67, a6, a7);

    const size_t row = (size_t)b * 2048 + (size_t)h * 32 + (s >> 6);
    float* dst = g_Y + row * EMB + ((s & 63) << 3);
    ((float4*)dst)[0] = make_float4(a0 * inv, a1 * inv, a2 * inv, a3 * inv);
    ((float4*)dst)[1] = make_float4(a4 * inv, a5 * inv, a6 * inv, a7 * inv);
}

// ---------------------------------------------------------------------------
// Kernel B: out[16384,512] = Y @ W^T + bias, tf32 mma.sync m16n8k8.
// R3: double-buffered smem + register-staged LDG prefetch — hides tile-load
// latency under MMA issue. One __syncthreads per k-tile.
// ---------------------------------------------------------------------------
__device__ __forceinline__ uint32_t f2tf(float f) {
    uint32_t r;
    asm("cvt.rna.tf32.f32 %0, %1;" : "=r"(r) : "f"(f));
    return r;
}

__global__ __launch_bounds__(256, 1) void gemm_kernel(const float* __restrict__ W,
                                                      const float* __restrict__ bias,
                                                      float* __restrict__ out) {
    // 36-elem rows: +4 pad keeps fragment LDS conflict-free; 144B row stride
    // is 16B-aligned so the 4-wide STS coalesces to STS.128.
    __shared__ uint32_t As[2][128][36];   // 36.9 KB
    __shared__ uint32_t Bs[2][128][36];   // 36.9 KB

    const int tid  = threadIdx.x;
    const int bm   = blockIdx.x;
    const int bn   = blockIdx.y;
    const int warp = tid >> 5;
    const int lane = tid & 31;
    const int wm   = warp >> 1;        // 0..3
    const int wn   = warp & 1;         // 0..1
    const int gID  = lane >> 2;        // 0..7
    const int tig  = lane & 3;         // 0..3

    float c[2][8][4];
#pragma unroll
    for (int mi = 0; mi < 2; ++mi)
#pragma unroll
        for (int ni = 0; ni < 8; ++ni)
#pragma unroll
            for (int k = 0; k < 4; ++k) c[mi][ni][k] = 0.f;

    const int lr = tid >> 3;           // 0..31
    const int lc = (tid & 7) << 2;     // 0,4,...,28

    const float* Abase = g_Y + ((size_t)bm * 128 + lr) * EMB + lc;
    const float* Bbase = W   + ((size_t)bn * 128 + lr) * EMB + lc;

    float4 va[4], vb[4];

    // Prologue: load k-tile 0 into buffer 0
#pragma unroll
    for (int p = 0; p < 4; ++p) {
        va[p] = *(const float4*)(Abase + (size_t)p * 32 * EMB);
        vb[p] = *(const float4*)(Bbase + (size_t)p * 32 * EMB);
    }
#pragma unroll
    for (int p = 0; p < 4; ++p) {
        uint32_t* da = &As[0][lr + p * 32][lc];
        da[0] = f2tf(va[p].x); da[1] = f2tf(va[p].y);
        da[2] = f2tf(va[p].z); da[3] = f2tf(va[p].w);
        uint32_t* db = &Bs[0][lr + p * 32][lc];
        db[0] = f2tf(vb[p].x); db[1] = f2tf(vb[p].y);
        db[2] = f2tf(vb[p].z); db[3] = f2tf(vb[p].w);
    }
    __syncthreads();

#pragma unroll 1
    for (int kt = 0; kt < 16; ++kt) {
        const int cur = kt & 1;
        const int nxt = cur ^ 1;

        // Prefetch next tile's LDGs first — they land while we do MMAs.
        if (kt < 15) {
            const int ko = (kt + 1) * 32;
#pragma unroll
            for (int p = 0; p < 4; ++p) {
                va[p] = *(const float4*)(Abase + (size_t)p * 32 * EMB + ko);
                vb[p] = *(const float4*)(Bbase + (size_t)p * 32 * EMB + ko);
            }
        }

        // Compute current tile
#pragma unroll
        for (int ks = 0; ks < 32; ks += 8) {
            uint32_t a[2][4];
#pragma unroll
            for (int mi = 0; mi < 2; ++mi) {
                int mrow = wm * 32 + mi * 16;
                a[mi][0] = As[cur][mrow + gID    ][ks + tig    ];
                a[mi][1] = As[cur][mrow + gID + 8][ks + tig    ];
                a[mi][2] = As[cur][mrow + gID    ][ks + tig + 4];
                a[mi][3] = As[cur][mrow + gID + 8][ks + tig + 4];
            }
#pragma unroll
            for (int ni = 0; ni < 8; ++ni) {
                int nrow = wn * 64 + ni * 8;
                uint32_t b0 = Bs[cur][nrow + gID][ks + tig    ];
                uint32_t b1 = Bs[cur][nrow + gID][ks + tig + 4];
#pragma unroll
                for (int mi = 0; mi < 2; ++mi) {
                    asm volatile(
                        "mma.sync.aligned.m16n8k8.row.col.f32.tf32.tf32.f32 "
                        "{%0,%1,%2,%3}, {%4,%5,%6,%7}, {%8,%9}, {%0,%1,%2,%3};"
                        : "+f"(c[mi][ni][0]), "+f"(c[mi][ni][1]),
                          "+f"(c[mi][ni][2]), "+f"(c[mi][ni][3])
                        : "r"(a[mi][0]), "r"(a[mi][1]), "r"(a[mi][2]), "r"(a[mi][3]),
                          "r"(b0), "r"(b1));
                }
            }
        }

        // Stage next tile into the other buffer. The sync at the end of the
        // previous iteration guarantees nobody is still reading buffer nxt.
        if (kt < 15) {
#pragma unroll
            for (int p = 0; p < 4; ++p) {
                uint32_t* da = &As[nxt][lr + p * 32][lc];
                da[0] = f2tf(va[p].x); da[1] = f2tf(va[p].y);
                da[2] = f2tf(va[p].z); da[3] = f2tf(va[p].w);
                uint32_t* db = &Bs[nxt][lr + p * 32][lc];
                db[0] = f2tf(vb[p].x); db[1] = f2tf(vb[p].y);
                db[2] = f2tf(vb[p].z); db[3] = f2tf(vb[p].w);
            }
            __syncthreads();
        }
    }

    // Epilogue: +bias, float2 stores
#pragma unroll
    for (int mi = 0; mi < 2; ++mi) {
        int row = bm * 128 + wm * 32 + mi * 16 + gID;
#pragma unroll
        for (int ni = 0; ni < 8; ++ni) {
            int col = bn * 128 + wn * 64 + ni * 8 + (tig << 1);
            float b0v = bias[col], b1v = bias[col + 1];
            float2 v0 = make_float2(c[mi][ni][0] + b0v, c[mi][ni][1] + b1v);
            float2 v1 = make_float2(c[mi][ni][2] + b0v, c[mi][ni][3] + b1v);
            *(float2*)(out + (size_t)row * EMB + col)       = v0;
            *(float2*)(out + (size_t)(row + 8) * EMB + col) = v1;
        }
    }
}

// ---------------------------------------------------------------------------
extern "C" void kernel_launch(void* const* d_in, const int* in_sizes, int n_in,
                              void* d_out, int out_size) {
    const float* x     = (const float*)d_in[0];   // (8, 2048, 512) f32
    const float* theta = (const float*)d_in[1];   // (8,) f32
    const float* Wc    = (const float*)d_in[2];   // (512, 512) f32
    const float* bc    = (const float*)d_in[3];   // (512,) f32
    float* out = (float*)d_out;                   // (8, 2048, 512) f32

    attn_kernel<<<NTOK / 4, 256>>>(x, theta);

    dim3 grid(NTOK / 128, EMB / 128);
    gemm_kernel<<<grid, 256>>>(Wc, bc, out);
}

// round 5
// speedup vs baseline: 1.0468x; 1.0468x over previous
#include <cuda_runtime.h>
#include <cstdint>

#define BATCH   8
#define S_LEN   2048
#define EMB     512
#define HEADS   64
#define DK      8
#define NTOK    (BATCH * S_LEN)   // 16384

// Scrambled attention output, values PRE-ROUNDED to tf32 precision.
__device__ float    g_Y[(size_t)NTOK * EMB];       // 33.5 MB
// W pre-rounded to tf32 bit patterns (row-major 512x512).
__device__ uint32_t g_Wtf[EMB * EMB];              // 1 MB

// ---------------------------------------------------------------------------
// Helpers
// ---------------------------------------------------------------------------
typedef unsigned long long u64;

__device__ __forceinline__ u64 pk2(float lo, float hi) {
    u64 r; asm("mov.b64 %0, {%1, %2};" : "=l"(r) : "f"(lo), "f"(hi)); return r;
}
__device__ __forceinline__ void upk2(u64 v, float& lo, float& hi) {
    asm("mov.b64 {%0, %1}, %2;" : "=f"(lo), "=f"(hi) : "l"(v));
}
__device__ __forceinline__ u64 fma2(u64 a, u64 b, u64 c) {
    u64 d; asm("fma.rn.f32x2 %0, %1, %2, %3;" : "=l"(d) : "l"(a), "l"(b), "l"(c)); return d;
}
__device__ __forceinline__ u64 mul2(u64 a, u64 b) {
    u64 d; asm("mul.rn.f32x2 %0, %1, %2;" : "=l"(d) : "l"(a), "l"(b)); return d;
}
__device__ __forceinline__ float ex2a(float x) {
    float r; asm("ex2.approx.f32 %0, %1;" : "=f"(r) : "f"(x)); return r;
}
__device__ __forceinline__ uint32_t f2tf(float f) {
    uint32_t r; asm("cvt.rna.tf32.f32 %0, %1;" : "=r"(r) : "f"(f)); return r;
}

// ---------------------------------------------------------------------------
// Kernel W: round W to tf32 once (runs in ~3us, replaces 128 re-conversions
// of every W element inside the GEMM's staging loop).
// ---------------------------------------------------------------------------
__global__ void wcvt_kernel(const float* __restrict__ W) {
    int i = (blockIdx.x * 256 + threadIdx.x) * 4;
    float4 v = *(const float4*)(W + i);
    uint4 o = make_uint4(f2tf(v.x), f2tf(v.y), f2tf(v.z), f2tf(v.w));
    *(uint4*)(g_Wtf + i) = o;
}

// ---------------------------------------------------------------------------
// Kernel A: quantum projection + head-axis attention, single-pass softmax.
// Unchanged from R2 except outputs are tf32-rounded (numerically identical
// to converting at GEMM staging time, which this replaces).
// ---------------------------------------------------------------------------
__global__ __launch_bounds__(256) void attn_kernel(const float* __restrict__ x,
                                                   const float* __restrict__ theta) {
    __shared__ __align__(16) float sproj[4][HEADS][DK];   // 8 KB

    const int tok_l = threadIdx.x >> 6;     // 0..3
    const int h     = threadIdx.x & 63;     // head row
    const int t     = (blockIdx.x << 2) + tok_l;
    const int b     = t >> 11;
    const int s     = t & 2047;

    const float4* xt  = (const float4*)(x + (size_t)t * EMB);
    const float4* th4 = (const float4*)theta;
    const float4 xa = xt[h * 2 + 0];
    const float4 xb = xt[h * 2 + 1];
    const float4 ta = th4[0];
    const float4 tb = th4[1];

    float p0 = cosf(xa.x + ta.x), p1 = cosf(xa.y + ta.y);
    float p2 = cosf(xa.z + ta.z), p3 = cosf(xa.w + ta.w);
    float p4 = cosf(xb.x + tb.x), p5 = cosf(xb.y + tb.y);
    float p6 = cosf(xb.z + tb.z), p7 = cosf(xb.w + tb.w);

    float4* sp = (float4*)&sproj[tok_l][h][0];
    sp[0] = make_float4(p0, p1, p2, p3);
    sp[1] = make_float4(p4, p5, p6, p7);
    __syncthreads();

    const u64 P01 = pk2(p0, p1), P23 = pk2(p2, p3);
    const u64 P45 = pk2(p4, p5), P67 = pk2(p6, p7);

    // scale = 1/sqrt(8) * log2(e); |score*scale| <= 4.1 so no max needed.
    const float SCALE = 0.35355339059327373f * 1.4426950408889634f;

    const ulonglong2* pj = (const ulonglong2*)&sproj[tok_l][0][0];

    float sum = 0.f;
    u64 A01 = 0, A23 = 0, A45 = 0, A67 = 0;

#pragma unroll 16
    for (int g = 0; g < 64; ++g) {
        ulonglong2 qa = pj[g * 2 + 0];
        ulonglong2 qb = pj[g * 2 + 1];

        u64 d2 = mul2(P01, qa.x);
        d2 = fma2(P23, qa.y, d2);
        d2 = fma2(P45, qb.x, d2);
        d2 = fma2(P67, qb.y, d2);
        float dlo, dhi; upk2(d2, dlo, dhi);

        float w = ex2a((dlo + dhi) * SCALE);
        sum += w;

        u64 ww = pk2(w, w);
        A01 = fma2(ww, qa.x, A01);
        A23 = fma2(ww, qa.y, A23);
        A45 = fma2(ww, qb.x, A45);
        A67 = fma2(ww, qb.y, A67);
    }

    const float inv = 1.0f / sum;
    float a0, a1, a2, a3, a4, a5, a6, a7;
    upk2(A01, a0, a1); upk2(A23, a2, a3);
    upk2(A45, a4, a5); upk2(A67, a6, a7);

    // tf32-rounded stores (bit patterns are valid fp32 with low mantissa = 0)
    const size_t row = (size_t)b * 2048 + (size_t)h * 32 + (s >> 6);
    uint32_t* dst = (uint32_t*)(g_Y + row * EMB + ((s & 63) << 3));
    ((uint4*)dst)[0] = make_uint4(f2tf(a0 * inv), f2tf(a1 * inv),
                                  f2tf(a2 * inv), f2tf(a3 * inv));
    ((uint4*)dst)[1] = make_uint4(f2tf(a4 * inv), f2tf(a5 * inv),
                                  f2tf(a6 * inv), f2tf(a7 * inv));
}

// ---------------------------------------------------------------------------
// Kernel B: out[16384,512] = Y @ W^T + bias, tf32 mma.sync m16n8k8.
// R4: double-buffered smem with COMPILE-TIME buffer indices (outer loop
// unrolled x2) + register-staged LDG prefetch; zero conversions in the loop.
// ---------------------------------------------------------------------------
__device__ __forceinline__ void ldg_tile(const uint32_t* Abase, const uint32_t* Bbase,
                                         int ko, uint4 va[4], uint4 vb[4]) {
#pragma unroll
    for (int p = 0; p < 4; ++p) {
        va[p] = *(const uint4*)(Abase + (size_t)p * 32 * EMB + ko);
        vb[p] = *(const uint4*)(Bbase + (size_t)p * 32 * EMB + ko);
    }
}

__device__ __forceinline__ void sts_tile(uint32_t (*As)[36], uint32_t (*Bs)[36],
                                         int lr, int lc,
                                         const uint4 va[4], const uint4 vb[4]) {
#pragma unroll
    for (int p = 0; p < 4; ++p) {
        *(uint4*)&As[lr + p * 32][lc] = va[p];
        *(uint4*)&Bs[lr + p * 32][lc] = vb[p];
    }
}

__device__ __forceinline__ void compute_tile(const uint32_t (*As)[36],
                                             const uint32_t (*Bs)[36],
                                             int wm, int wn, int gID, int tig,
                                             float c[2][8][4]) {
#pragma unroll
    for (int ks = 0; ks < 32; ks += 8) {
        uint32_t a[2][4];
#pragma unroll
        for (int mi = 0; mi < 2; ++mi) {
            int mrow = wm * 32 + mi * 16;
            a[mi][0] = As[mrow + gID    ][ks + tig    ];
            a[mi][1] = As[mrow + gID + 8][ks + tig    ];
            a[mi][2] = As[mrow + gID    ][ks + tig + 4];
            a[mi][3] = As[mrow + gID + 8][ks + tig + 4];
        }
#pragma unroll
        for (int ni = 0; ni < 8; ++ni) {
            int nrow = wn * 64 + ni * 8;
            uint32_t b0 = Bs[nrow + gID][ks + tig    ];
            uint32_t b1 = Bs[nrow + gID][ks + tig + 4];
#pragma unroll
            for (int mi = 0; mi < 2; ++mi) {
                asm volatile(
                    "mma.sync.aligned.m16n8k8.row.col.f32.tf32.tf32.f32 "
                    "{%0,%1,%2,%3}, {%4,%5,%6,%7}, {%8,%9}, {%0,%1,%2,%3};"
                    : "+f"(c[mi][ni][0]), "+f"(c[mi][ni][1]),
                      "+f"(c[mi][ni][2]), "+f"(c[mi][ni][3])
                    : "r"(a[mi][0]), "r"(a[mi][1]), "r"(a[mi][2]), "r"(a[mi][3]),
                      "r"(b0), "r"(b1));
            }
        }
    }
}

__global__ __launch_bounds__(256, 1) void gemm_kernel(const float* __restrict__ bias,
                                                      float* __restrict__ out) {
    // +4 pad: fragment LDS bank = 4*gID + tig — conflict-free; 144B row
    // stride keeps uint4 STS 16B-aligned.
    __shared__ uint32_t As[2][128][36];   // 36.9 KB
    __shared__ uint32_t Bs[2][128][36];   // 36.9 KB

    const int tid  = threadIdx.x;
    const int bm   = blockIdx.x;
    const int bn   = blockIdx.y;
    const int warp = tid >> 5;
    const int lane = tid & 31;
    const int wm   = warp >> 1;        // 0..3
    const int wn   = warp & 1;         // 0..1
    const int gID  = lane >> 2;        // 0..7
    const int tig  = lane & 3;         // 0..3

    float c[2][8][4];
#pragma unroll
    for (int mi = 0; mi < 2; ++mi)
#pragma unroll
        for (int ni = 0; ni < 8; ++ni)
#pragma unroll
            for (int k = 0; k < 4; ++k) c[mi][ni][k] = 0.f;

    const int lr = tid >> 3;           // 0..31
    const int lc = (tid & 7) << 2;     // 0,4,...,28

    const uint32_t* Abase = (const uint32_t*)g_Y + ((size_t)bm * 128 + lr) * EMB + lc;
    const uint32_t* Bbase = g_Wtf + ((size_t)bn * 128 + lr) * EMB + lc;

    uint4 va[4], vb[4];

    // Prologue: tile 0 -> buf0
    ldg_tile(Abase, Bbase, 0, va, vb);
    sts_tile(As[0], Bs[0], lr, lc, va, vb);
    __syncthreads();

#pragma unroll 1
    for (int kt = 0; kt < 16; kt += 2) {
        // --- even tile: compute buf0, stage kt+1 into buf1 ---
        ldg_tile(Abase, Bbase, (kt + 1) * 32, va, vb);
        compute_tile(As[0], Bs[0], wm, wn, gID, tig, c);
        sts_tile(As[1], Bs[1], lr, lc, va, vb);
        __syncthreads();

        // --- odd tile: compute buf1, stage kt+2 into buf0 ---
        if (kt + 2 < 16)
            ldg_tile(Abase, Bbase, (kt + 2) * 32, va, vb);
        compute_tile(As[1], Bs[1], wm, wn, gID, tig, c);
        if (kt + 2 < 16) {
            sts_tile(As[0], Bs[0], lr, lc, va, vb);
            __syncthreads();
        }
    }

    // Epilogue: +bias, float2 stores
#pragma unroll
    for (int mi = 0; mi < 2; ++mi) {
        int row = bm * 128 + wm * 32 + mi * 16 + gID;
#pragma unroll
        for (int ni = 0; ni < 8; ++ni) {
            int col = bn * 128 + wn * 64 + ni * 8 + (tig << 1);
            float b0v = bias[col], b1v = bias[col + 1];
            float2 v0 = make_float2(c[mi][ni][0] + b0v, c[mi][ni][1] + b1v);
            float2 v1 = make_float2(c[mi][ni][2] + b0v, c[mi][ni][3] + b1v);
            *(float2*)(out + (size_t)row * EMB + col)       = v0;
            *(float2*)(out + (size_t)(row + 8) * EMB + col) = v1;
        }
    }
}

// ---------------------------------------------------------------------------
extern "C" void kernel_launch(void* const* d_in, const int* in_sizes, int n_in,
                              void* d_out, int out_size) {
    const float* x     = (const float*)d_in[0];   // (8, 2048, 512) f32
    const float* theta = (const float*)d_in[1];   // (8,) f32
    const float* Wc    = (const float*)d_in[2];   // (512, 512) f32
    const float* bc    = (const float*)d_in[3];   // (512,) f32
    float* out = (float*)d_out;                   // (8, 2048, 512) f32

    wcvt_kernel<<<EMB * EMB / 1024, 256>>>(Wc);
    attn_kernel<<<NTOK / 4, 256>>>(x, theta);

    dim3 grid(NTOK / 128, EMB / 128);
    gemm_kernel<<<grid, 256>>>(bc, out);
}

// round 6
// speedup vs baseline: 1.7016x; 1.6255x over previous
#include <cuda_runtime.h>
#include <cstdint>

#define BATCH   8
#define S_LEN   2048
#define EMB     512
#define HEADS   64
#define DK      8
#define NTOK    (BATCH * S_LEN)   // 16384

// Scrambled attention output, values PRE-ROUNDED to tf32 precision.
__device__ float    g_Y[(size_t)NTOK * EMB];       // 33.5 MB
// W pre-rounded to tf32 bit patterns (row-major 512x512).
__device__ uint32_t g_Wtf[EMB * EMB];              // 1 MB

// ---------------------------------------------------------------------------
// Helpers
// ---------------------------------------------------------------------------
typedef unsigned long long u64;

__device__ __forceinline__ u64 pk2(float lo, float hi) {
    u64 r; asm("mov.b64 %0, {%1, %2};" : "=l"(r) : "f"(lo), "f"(hi)); return r;
}
__device__ __forceinline__ void upk2(u64 v, float& lo, float& hi) {
    asm("mov.b64 {%0, %1}, %2;" : "=f"(lo), "=f"(hi) : "l"(v));
}
__device__ __forceinline__ u64 fma2(u64 a, u64 b, u64 c) {
    u64 d; asm("fma.rn.f32x2 %0, %1, %2, %3;" : "=l"(d) : "l"(a), "l"(b), "l"(c)); return d;
}
__device__ __forceinline__ u64 mul2(u64 a, u64 b) {
    u64 d; asm("mul.rn.f32x2 %0, %1, %2;" : "=l"(d) : "l"(a), "l"(b)); return d;
}
__device__ __forceinline__ float ex2a(float x) {
    float r; asm("ex2.approx.f32 %0, %1;" : "=f"(r) : "f"(x)); return r;
}
__device__ __forceinline__ uint32_t f2tf(float f) {
    uint32_t r; asm("cvt.rna.tf32.f32 %0, %1;" : "=r"(r) : "f"(f)); return r;
}

// ---------------------------------------------------------------------------
// Kernel W: round W to tf32 once.
// ---------------------------------------------------------------------------
__global__ void wcvt_kernel(const float* __restrict__ W) {
    int i = (blockIdx.x * 256 + threadIdx.x) * 4;
    float4 v = *(const float4*)(W + i);
    uint4 o = make_uint4(f2tf(v.x), f2tf(v.y), f2tf(v.z), f2tf(v.w));
    *(uint4*)(g_Wtf + i) = o;
}

// ---------------------------------------------------------------------------
// Kernel A: quantum projection + head-axis attention, single-pass softmax.
// (unchanged; ~63us)
// ---------------------------------------------------------------------------
__global__ __launch_bounds__(256) void attn_kernel(const float* __restrict__ x,
                                                   const float* __restrict__ theta) {
    __shared__ __align__(16) float sproj[4][HEADS][DK];   // 8 KB

    const int tok_l = threadIdx.x >> 6;     // 0..3
    const int h     = threadIdx.x & 63;     // head row
    const int t     = (blockIdx.x << 2) + tok_l;
    const int b     = t >> 11;
    const int s     = t & 2047;

    const float4* xt  = (const float4*)(x + (size_t)t * EMB);
    const float4* th4 = (const float4*)theta;
    const float4 xa = xt[h * 2 + 0];
    const float4 xb = xt[h * 2 + 1];
    const float4 ta = th4[0];
    const float4 tb = th4[1];

    float p0 = cosf(xa.x + ta.x), p1 = cosf(xa.y + ta.y);
    float p2 = cosf(xa.z + ta.z), p3 = cosf(xa.w + ta.w);
    float p4 = cosf(xb.x + tb.x), p5 = cosf(xb.y + tb.y);
    float p6 = cosf(xb.z + tb.z), p7 = cosf(xb.w + tb.w);

    float4* sp = (float4*)&sproj[tok_l][h][0];
    sp[0] = make_float4(p0, p1, p2, p3);
    sp[1] = make_float4(p4, p5, p6, p7);
    __syncthreads();

    const u64 P01 = pk2(p0, p1), P23 = pk2(p2, p3);
    const u64 P45 = pk2(p4, p5), P67 = pk2(p6, p7);

    // scale = 1/sqrt(8) * log2(e); |score*scale| <= 4.1 so no max needed.
    const float SCALE = 0.35355339059327373f * 1.4426950408889634f;

    const ulonglong2* pj = (const ulonglong2*)&sproj[tok_l][0][0];

    float sum = 0.f;
    u64 A01 = 0, A23 = 0, A45 = 0, A67 = 0;

#pragma unroll 16
    for (int g = 0; g < 64; ++g) {
        ulonglong2 qa = pj[g * 2 + 0];
        ulonglong2 qb = pj[g * 2 + 1];

        u64 d2 = mul2(P01, qa.x);
        d2 = fma2(P23, qa.y, d2);
        d2 = fma2(P45, qb.x, d2);
        d2 = fma2(P67, qb.y, d2);
        float dlo, dhi; upk2(d2, dlo, dhi);

        float w = ex2a((dlo + dhi) * SCALE);
        sum += w;

        u64 ww = pk2(w, w);
        A01 = fma2(ww, qa.x, A01);
        A23 = fma2(ww, qa.y, A23);
        A45 = fma2(ww, qb.x, A45);
        A67 = fma2(ww, qb.y, A67);
    }

    const float inv = 1.0f / sum;
    float a0, a1, a2, a3, a4, a5, a6, a7;
    upk2(A01, a0, a1); upk2(A23, a2, a3);
    upk2(A45, a4, a5); upk2(A67, a6, a7);

    // tf32-rounded stores (valid fp32 bit patterns, low mantissa zero)
    const size_t row = (size_t)b * 2048 + (size_t)h * 32 + (s >> 6);
    uint32_t* dst = (uint32_t*)(g_Y + row * EMB + ((s & 63) << 3));
    ((uint4*)dst)[0] = make_uint4(f2tf(a0 * inv), f2tf(a1 * inv),
                                  f2tf(a2 * inv), f2tf(a3 * inv));
    ((uint4*)dst)[1] = make_uint4(f2tf(a4 * inv), f2tf(a5 * inv),
                                  f2tf(a6 * inv), f2tf(a7 * inv));
}

// ---------------------------------------------------------------------------
// Kernel B: out[16384,512] = Y @ W^T + bias, tf32 mma.sync m16n8k8.
// R5: cp.async (LDGSTS) staging — ZERO register staging — double-buffered,
// compile-time buffer indices, wait_group-deferred pipeline.
// ---------------------------------------------------------------------------
#define CP_ASYNC16(smem_u32, gptr) \
    asm volatile("cp.async.cg.shared.global [%0], [%1], 16;" \
                 :: "r"(smem_u32), "l"(gptr) : "memory")
#define CP_COMMIT()  asm volatile("cp.async.commit_group;" ::: "memory")
#define CP_WAIT(N)   asm volatile("cp.async.wait_group %0;" :: "n"(N) : "memory")

// Row stride = 36 u32 = 144 B (pad keeps fragment LDS conflict-free and
// 16B-aligned for cp.async).
#define ROWB 144

__device__ __forceinline__ void cpa_tile(const uint32_t* Abase, const uint32_t* Bbase,
                                         int ko, uint32_t sA, uint32_t sB) {
#pragma unroll
    for (int p = 0; p < 4; ++p) {
        CP_ASYNC16(sA + p * 32 * ROWB, Abase + (size_t)p * 32 * EMB + ko);
        CP_ASYNC16(sB + p * 32 * ROWB, Bbase + (size_t)p * 32 * EMB + ko);
    }
    CP_COMMIT();
}

__device__ __forceinline__ void compute_tile(const uint32_t (*As)[36],
                                             const uint32_t (*Bs)[36],
                                             int wm, int wn, int gID, int tig,
                                             float c[2][8][4]) {
#pragma unroll
    for (int ks = 0; ks < 32; ks += 8) {
        uint32_t a[2][4];
#pragma unroll
        for (int mi = 0; mi < 2; ++mi) {
            int mrow = wm * 32 + mi * 16;
            a[mi][0] = As[mrow + gID    ][ks + tig    ];
            a[mi][1] = As[mrow + gID + 8][ks + tig    ];
            a[mi][2] = As[mrow + gID    ][ks + tig + 4];
            a[mi][3] = As[mrow + gID + 8][ks + tig + 4];
        }
#pragma unroll
        for (int ni = 0; ni < 8; ++ni) {
            int nrow = wn * 64 + ni * 8;
            uint32_t b0 = Bs[nrow + gID][ks + tig    ];
            uint32_t b1 = Bs[nrow + gID][ks + tig + 4];
#pragma unroll
            for (int mi = 0; mi < 2; ++mi) {
                asm volatile(
                    "mma.sync.aligned.m16n8k8.row.col.f32.tf32.tf32.f32 "
                    "{%0,%1,%2,%3}, {%4,%5,%6,%7}, {%8,%9}, {%0,%1,%2,%3};"
                    : "+f"(c[mi][ni][0]), "+f"(c[mi][ni][1]),
                      "+f"(c[mi][ni][2]), "+f"(c[mi][ni][3])
                    : "r"(a[mi][0]), "r"(a[mi][1]), "r"(a[mi][2]), "r"(a[mi][3]),
                      "r"(b0), "r"(b1));
            }
        }
    }
}

__global__ __launch_bounds__(256, 2) void gemm_kernel(const float* __restrict__ bias,
                                                      float* __restrict__ out) {
    __shared__ uint32_t As[2][128][36];   // 36.9 KB
    __shared__ uint32_t Bs[2][128][36];   // 36.9 KB

    const int tid  = threadIdx.x;
    const int bm   = blockIdx.x;
    const int bn   = blockIdx.y;
    const int warp = tid >> 5;
    const int lane = tid & 31;
    const int wm   = warp >> 1;        // 0..3
    const int wn   = warp & 1;         // 0..1
    const int gID  = lane >> 2;        // 0..7
    const int tig  = lane & 3;         // 0..3

    float c[2][8][4];
#pragma unroll
    for (int mi = 0; mi < 2; ++mi)
#pragma unroll
        for (int ni = 0; ni < 8; ++ni)
#pragma unroll
            for (int k = 0; k < 4; ++k) c[mi][ni][k] = 0.f;

    const int lr = tid >> 3;           // 0..31
    const int lc = (tid & 7) << 2;     // 0,4,...,28

    const uint32_t* Abase = (const uint32_t*)g_Y + ((size_t)bm * 128 + lr) * EMB + lc;
    const uint32_t* Bbase = g_Wtf + ((size_t)bn * 128 + lr) * EMB + lc;

    const uint32_t sA0 = (uint32_t)__cvta_generic_to_shared(&As[0][lr][lc]);
    const uint32_t sB0 = (uint32_t)__cvta_generic_to_shared(&Bs[0][lr][lc]);
    const uint32_t sA1 = (uint32_t)__cvta_generic_to_shared(&As[1][lr][lc]);
    const uint32_t sB1 = (uint32_t)__cvta_generic_to_shared(&Bs[1][lr][lc]);

    // Prologue: tiles 0 and 1 in flight; wait for tile 0.
    cpa_tile(Abase, Bbase, 0,  sA0, sB0);
    cpa_tile(Abase, Bbase, 32, sA1, sB1);
    CP_WAIT(1);
    __syncthreads();

#pragma unroll 1
    for (int kt = 0; kt < 16; kt += 2) {
        // tile kt ready in buf0
        compute_tile(As[0], Bs[0], wm, wn, gID, tig, c);
        __syncthreads();                       // everyone done reading buf0
        if (kt + 2 < 16) {
            cpa_tile(Abase, Bbase, (kt + 2) * 32, sA0, sB0);
            CP_WAIT(1);                        // tile kt+1 (buf1) landed
        } else {
            CP_WAIT(0);                        // tail: drain tile 15
        }
        __syncthreads();

        // tile kt+1 ready in buf1
        compute_tile(As[1], Bs[1], wm, wn, gID, tig, c);
        __syncthreads();                       // everyone done reading buf1
        if (kt + 3 < 16) {
            cpa_tile(Abase, Bbase, (kt + 3) * 32, sA1, sB1);
            CP_WAIT(1);                        // tile kt+2 (buf0) landed
            __syncthreads();
        }
    }

    // Epilogue: +bias, float2 stores
#pragma unroll
    for (int mi = 0; mi < 2; ++mi) {
        int row = bm * 128 + wm * 32 + mi * 16 + gID;
#pragma unroll
        for (int ni = 0; ni < 8; ++ni) {
            int col = bn * 128 + wn * 64 + ni * 8 + (tig << 1);
            float b0v = bias[col], b1v = bias[col + 1];
            float2 v0 = make_float2(c[mi][ni][0] + b0v, c[mi][ni][1] + b1v);
            float2 v1 = make_float2(c[mi][ni][2] + b0v, c[mi][ni][3] + b1v);
            *(float2*)(out + (size_t)row * EMB + col)       = v0;
            *(float2*)(out + (size_t)(row + 8) * EMB + col) = v1;
        }
    }
}

// ---------------------------------------------------------------------------
extern "C" void kernel_launch(void* const* d_in, const int* in_sizes, int n_in,
                              void* d_out, int out_size) {
    const float* x     = (const float*)d_in[0];   // (8, 2048, 512) f32
    const float* theta = (const float*)d_in[1];   // (8,) f32
    const float* Wc    = (const float*)d_in[2];   // (512, 512) f32
    const float* bc    = (const float*)d_in[3];   // (512,) f32
    float* out = (float*)d_out;                   // (8, 2048, 512) f32

    wcvt_kernel<<<EMB * EMB / 1024, 256>>>(Wc);
    attn_kernel<<<NTOK / 4, 256>>>(x, theta);

    dim3 grid(NTOK / 128, EMB / 128);
    gemm_kernel<<<grid, 256>>>(bc, out);
}